// round 3
// baseline (speedup 1.0000x reference)
#include <cuda_runtime.h>
#include <cuda_bf16.h>

#define BSZ 64
#define NC  32

// Spatial sizes: 255 -> 127 -> 63 -> 31 -> 15 -> 7 (stride 2, VALID, k=3)
static const int H0 = 255, H1 = 127, H2 = 63, H3 = 31, H4 = 15, H5 = 7;

// ---------------- scratch ----------------
__device__ float g_bufA[BSZ * NC * 127 * 127];
__device__ float g_bufB[BSZ * NC * 63 * 63];
__device__ float g_feat[BSZ * NC * 7 * 7];
__device__ float g_fc1[BSZ * 20];
__device__ float g_coef[BSZ * 27];

// ---------------- unified conv: ICN -> 32, stride 2, fused bias+relu+bn ----------------
// 4 output pixels x OCG output channels per thread. blockIdx.y = channel group.
// Weight layout: w[oc][ic][ky][kx], oc in [g*OCG, (g+1)*OCG).
template <int HIN, int HOUT, int ICN, int OCG>
__global__ void __launch_bounds__(128) conv_kernel(
    const float* __restrict__ x, const float* __restrict__ w,
    const float* __restrict__ cbias,
    const float* __restrict__ bng, const float* __restrict__ bnb,
    const float* __restrict__ bnm, const float* __restrict__ bnv,
    float* __restrict__ out)
{
    constexpr int NXP = (HOUT + 3) / 4;
    __shared__ float ws[OCG * ICN * 9];
    __shared__ float sc_s[OCG], sh_s[OCG], bias_s[OCG];

    const int g   = blockIdx.y;
    const int oc0 = g * OCG;

    for (int i = threadIdx.x; i < OCG * ICN * 9; i += blockDim.x)
        ws[i] = w[oc0 * ICN * 9 + i];
    if (threadIdx.x < OCG) {
        int oc = oc0 + threadIdx.x;
        float sc = bng[oc] * rsqrtf(bnv[oc] + 1e-5f);
        sc_s[threadIdx.x]   = sc;
        sh_s[threadIdx.x]   = bnb[oc] - bnm[oc] * sc;
        bias_s[threadIdx.x] = cbias[oc];
    }
    __syncthreads();

    int idx = blockIdx.x * blockDim.x + threadIdx.x;
    int total = BSZ * HOUT * NXP;
    if (idx >= total) return;
    int xp = idx % NXP;
    int t  = idx / NXP;
    int oy = t % HOUT;
    int b  = t / HOUT;
    int ox0 = 4 * xp;
    bool full = (ox0 + 3) < HOUT;   // implies input x-extent 2*ox0+8 <= HIN-1 (HIN = 2*HOUT+1)

    float acc[4][OCG];
#pragma unroll
    for (int j = 0; j < 4; ++j)
#pragma unroll
        for (int oc = 0; oc < OCG; ++oc) acc[j][oc] = 0.f;

    const float* xb = x + ((size_t)(b * ICN) * HIN + 2 * oy) * HIN + 2 * ox0;

    for (int ic = 0; ic < ICN; ++ic) {
        const float* xc = xb + (size_t)ic * HIN * HIN;
#pragma unroll
        for (int ky = 0; ky < 3; ++ky) {
            const float* row = xc + ky * HIN;
            float xin[9];
            if (full) {
#pragma unroll
                for (int i = 0; i < 9; ++i) xin[i] = row[i];
            } else {
#pragma unroll
                for (int i = 0; i < 9; ++i)
                    xin[i] = (2 * ox0 + i < HIN) ? row[i] : 0.f;
            }
#pragma unroll
            for (int kx = 0; kx < 3; ++kx) {
                const float* wp = ws + ic * 9 + ky * 3 + kx;
#pragma unroll
                for (int oc = 0; oc < OCG; ++oc) {
                    float wv = wp[oc * ICN * 9];
#pragma unroll
                    for (int j = 0; j < 4; ++j)
                        acc[j][oc] = fmaf(xin[2 * j + kx], wv, acc[j][oc]);
                }
            }
        }
    }

    size_t obase = ((size_t)(b * NC + oc0) * HOUT + oy) * HOUT + ox0;
#pragma unroll
    for (int oc = 0; oc < OCG; ++oc) {
#pragma unroll
        for (int j = 0; j < 4; ++j) {
            if (full || (ox0 + j) < HOUT) {
                float y = fmaxf(acc[j][oc] + bias_s[oc], 0.f) * sc_s[oc] + sh_s[oc];
                out[obase + (size_t)oc * HOUT * HOUT + j] = y;
            }
        }
    }
}

// ---------------- FC1: [64,1568] @ [1568,20]^T + b, relu ----------------
__global__ void fc1_kernel(const float* __restrict__ feat, const float* __restrict__ w,
                           const float* __restrict__ bias, float* __restrict__ out)
{
    int gw   = (blockIdx.x * blockDim.x + threadIdx.x) >> 5;
    int lane = threadIdx.x & 31;
    if (gw >= BSZ * 20) return;
    int j = gw % 20, b = gw / 20;
    const float* f  = feat + b * 1568;
    const float* wr = w + j * 1568;
    float s = 0.f;
    for (int k = lane; k < 1568; k += 32) s = fmaf(f[k], wr[k], s);
#pragma unroll
    for (int o = 16; o; o >>= 1) s += __shfl_xor_sync(0xffffffffu, s, o);
    if (lane == 0) out[b * 20 + j] = fmaxf(s + bias[j], 0.f);
}

// ---------------- FC2 + cubic-spline solve (Thomas) ----------------
__global__ void spline_kernel(const float* __restrict__ fc1,
                              const float* __restrict__ l2w, const float* __restrict__ l2b,
                              float* __restrict__ coef)
{
    int b = blockIdx.x * blockDim.x + threadIdx.x;
    if (b >= BSZ) return;

    float ys[10];
#pragma unroll
    for (int k = 0; k < 10; ++k) {
        float s = l2b[k];
#pragma unroll
        for (int j = 0; j < 20; ++j) s = fmaf(fc1[b * 20 + j], l2w[k * 20 + j], s);
        ys[k] = s;
    }

    const float h = (float)(1.0 / 9.0);
    const float c6h2 = 6.0f * 81.0f;
    float d[8];
#pragma unroll
    for (int i = 0; i < 8; ++i) d[i] = c6h2 * (ys[i] - 2.f * ys[i + 1] + ys[i + 2]);

    float cp[8], dp[8];
    cp[0] = 0.25f; dp[0] = d[0] * 0.25f;
#pragma unroll
    for (int i = 1; i < 8; ++i) {
        float mden = 4.f - cp[i - 1];
        cp[i] = 1.f / mden;
        dp[i] = (d[i] - dp[i - 1]) / mden;
    }
    float M[10];
    M[0] = 0.f; M[9] = 0.f;
    M[8] = dp[7];
#pragma unroll
    for (int i = 6; i >= 0; --i) M[i + 1] = dp[i] - cp[i] * M[i + 2];

#pragma unroll
    for (int i = 0; i < 9; ++i) {
        coef[b * 27 + i]      = (M[i + 1] - M[i]) / (6.f * h);
        coef[b * 27 + 9 + i]  = M[i] * 0.5f;
        coef[b * 27 + 18 + i] = (ys[i + 1] - ys[i]) / h - (M[i + 1] + 2.f * M[i]) * (h / 6.f);
    }
}

// ---------------- final fused bucketize + gather + cubic eval (float4) ----------------
__global__ void eval_kernel(const float4* __restrict__ x, const float* __restrict__ coef,
                            float4* __restrict__ out, int n4)
{
    int idx = blockIdx.x * blockDim.x + threadIdx.x;
    if (idx >= n4) return;
    const int per = 3 * 255 * 255;
    int i0 = idx * 4;
    int b0 = i0 / per;
    int r0 = i0 - b0 * per;

    float4 xv = x[idx];
    float vals[4] = {xv.x, xv.y, xv.z, xv.w};
    float res[4];
    const float h = (float)(1.0 / 9.0);
#pragma unroll
    for (int j = 0; j < 4; ++j) {
        int b = b0 + ((r0 + j) >= per ? 1 : 0);
        float v = vals[j];
        float q = fminf(fmaxf(v / h, 0.f), 8.f);
        int xi = (int)floorf(q);
        float xf = v - (float)xi * h;
        const float* cf = coef + b * 27;
        float a  = __ldg(cf + xi);
        float bb = __ldg(cf + 9 + xi);
        float cc = __ldg(cf + 18 + xi);
        res[j] = ((a * xf + bb) * xf + cc) * xf;
    }
    out[idx] = make_float4(res[0], res[1], res[2], res[3]);
}

// ---------------- launch ----------------
extern "C" void kernel_launch(void* const* d_in, const int* in_sizes, int n_in,
                              void* d_out, int out_size)
{
    const float* batch = (const float*)d_in[0];
    const float* c1_w  = (const float*)d_in[1];
    const float* c1_b  = (const float*)d_in[2];
    const float* cw    = (const float*)d_in[3];
    const float* cb    = (const float*)d_in[4];
    const float* bn_g  = (const float*)d_in[5];
    const float* bn_b  = (const float*)d_in[6];
    const float* bn_m  = (const float*)d_in[7];
    const float* bn_v  = (const float*)d_in[8];
    const float* l1_w  = (const float*)d_in[9];
    const float* l1_b  = (const float*)d_in[10];
    const float* l2_w  = (const float*)d_in[11];
    const float* l2_b  = (const float*)d_in[12];
    float* out = (float*)d_out;

    float* bufA; cudaGetSymbolAddress((void**)&bufA, g_bufA);
    float* bufB; cudaGetSymbolAddress((void**)&bufB, g_bufB);
    float* feat; cudaGetSymbolAddress((void**)&feat, g_feat);
    float* fc1;  cudaGetSymbolAddress((void**)&fc1,  g_fc1);
    float* coef; cudaGetSymbolAddress((void**)&coef, g_coef);

    const int TB = 128;

    // conv1: 3 -> 32, 255 -> 127.  OCG=16, 2 groups.
    {
        constexpr int NXP = (H1 + 3) / 4;           // 32
        int total = BSZ * H1 * NXP;                  // 260096
        dim3 grid((total + TB - 1) / TB, NC / 16);
        conv_kernel<H0, H1, 3, 16><<<grid, TB>>>(
            batch, c1_w, c1_b, bn_g, bn_b, bn_m, bn_v, bufA);
    }
    // conv2: 32 -> 32, 127 -> 63.  OCG=16, 2 groups.
    {
        constexpr int NXP = (H2 + 3) / 4;           // 16
        int total = BSZ * H2 * NXP;                  // 64512
        dim3 grid((total + TB - 1) / TB, NC / 16);
        conv_kernel<H1, H2, NC, 16><<<grid, TB>>>(
            bufA, cw + 0 * NC * NC * 9, cb + 0 * NC,
            bn_g + 1 * NC, bn_b + 1 * NC, bn_m + 1 * NC, bn_v + 1 * NC, bufB);
    }
    // conv3: 63 -> 31.  OCG=8, 4 groups.
    {
        constexpr int NXP = (H3 + 3) / 4;           // 8
        int total = BSZ * H3 * NXP;                  // 15872
        dim3 grid((total + TB - 1) / TB, NC / 8);
        conv_kernel<H2, H3, NC, 8><<<grid, TB>>>(
            bufB, cw + 1 * NC * NC * 9, cb + 1 * NC,
            bn_g + 2 * NC, bn_b + 2 * NC, bn_m + 2 * NC, bn_v + 2 * NC, bufA);
    }
    // conv4: 31 -> 15.  OCG=2, 16 groups -> 480 blocks.
    {
        constexpr int NXP = (H4 + 3) / 4;           // 4
        int total = BSZ * H4 * NXP;                  // 3840
        dim3 grid((total + TB - 1) / TB, NC / 2);
        conv_kernel<H3, H4, NC, 2><<<grid, TB>>>(
            bufA, cw + 2 * NC * NC * 9, cb + 2 * NC,
            bn_g + 3 * NC, bn_b + 3 * NC, bn_m + 3 * NC, bn_v + 3 * NC, bufB);
    }
    // conv5: 15 -> 7.  OCG=2, 16 groups -> 112 blocks.
    {
        constexpr int NXP = (H5 + 3) / 4;           // 2
        int total = BSZ * H5 * NXP;                  // 896
        dim3 grid((total + TB - 1) / TB, NC / 2);
        conv_kernel<H4, H5, NC, 2><<<grid, TB>>>(
            bufB, cw + 3 * NC * NC * 9, cb + 3 * NC,
            bn_g + 4 * NC, bn_b + 4 * NC, bn_m + 4 * NC, bn_v + 4 * NC, feat);
    }
    // FC1
    {
        int warps = BSZ * 20;
        int threads = warps * 32;
        fc1_kernel<<<(threads + 255) / 256, 256>>>(feat, l1_w, l1_b, fc1);
    }
    // FC2 + spline solve
    spline_kernel<<<1, BSZ>>>(fc1, l2_w, l2_b, coef);

    // Final fused eval
    {
        int n4 = out_size / 4;
        eval_kernel<<<(n4 + 255) / 256, 256>>>((const float4*)batch, coef, (float4*)out, n4);
    }
}